// round 13
// baseline (speedup 1.0000x reference)
#include <cuda_runtime.h>

// QuConvSXZ: 12-qubit pairwise-gate circuit + partial trace (REAL part out).
//
//   phi = U psi;  out[i,j] = Re( sum_t phi[t*64+i] * conj(phi[t*64+j]) )
// Gates on traced (leading) qubits cancel by unitarity; only pairs 3,4,5 act,
// on base-4 digits (5,4),(3,2),(1,0) of the kept index; each gate is
// diag+antidiag {a,b,d,e} (analytic form silicon-validated R1==R2).
//
// R12: warp-owned trace. phi stored in smem as float4 slots with XOR swizzle
//   phys_slot(t,s) = s ^ (s>>3) ^ (t&7)
// making evolution STS.128, column-wise vj LDS.128 and vi LDS.64 all
// (nearly) conflict-free. Each warp owns (row r2, j-quad); lane = t;
// butterfly-reduce + one STG.128. No barrier #2, no partials array, no tail.
// Gate broadcast via 6 producer lanes + variable-src shfl (16 shfls).

#define NTHREADS 1024

typedef float2 cplx;

__global__ __launch_bounds__(NTHREADS, 1)
void quconv_kernel(const float* __restrict__ x,
                   const float* __restrict__ w,
                   float* __restrict__ out)
{
    __shared__ float4 psi4[2048];      // 32 KB phi, swizzled slots

    const int tid    = threadIdx.x;
    const int batch  = blockIdx.y;
    const int islice = blockIdx.x;     // 0..31
    const int lane   = tid & 31;
    const int warp   = tid >> 5;
    const unsigned FULL = 0xffffffffu;

    // ---- issue x load immediately ----
    const float4 xv = ((const float4*)(x + batch * 4096))[tid];

    // ---- gate producers: lanes 0..5. pair = 3+(lane>>1), kind = lane&1
    //      kind 0 = outer {a,b}:  D=a=(c3*cu,-s3*cu), A=b=(-s3*su,-c3*su), u=t1-t2
    //      kind 1 = inner {d,e}:  D=d=(c3*cv, s3*cv), A=e=( s3*sv,-c3*sv), v=t1+t2
    float Dp = 0.f, Dq = 0.f, Ap = 0.f, Aq = 0.f;
    if (lane < 6) {
        const float WH = 0.31622776601683794f;   // sqrt(2/5)/2
        const int pr   = lane >> 1;              // 0,1,2 -> pairs 3,4,5
        const int kind = lane & 1;
        const int idx  = 54 + 6 * pr;
        float t1 = w[idx] * WH, t2 = w[idx + 1] * WH, t3 = w[idx + 2] * WH;
        float u = kind ? (t1 + t2) : (t1 - t2);
        float su, cu, s3, c3;
        __sincosf(u,  &su, &cu);
        __sincosf(t3, &s3, &c3);
        float s3p = kind ? s3 : -s3;
        Dp = c3 * cu;   Dq = s3p * cu;
        Ap = s3p * su;  Aq = -c3 * su;
    }

    // ---- register evolution ----
    const int s1v = lane & 3;          // digit (3,2)
    const int s2v = (lane >> 2) & 3;   // digit (5,4)

    cplx o0, o1, o2, o3;
    {   // stage A: pair 5 (lanes 4=ab, 5=de), digit (1,0) intra-thread, REAL in
        const float ax = __shfl_sync(FULL, Dp, 4), ay = __shfl_sync(FULL, Dq, 4);
        const float bx = __shfl_sync(FULL, Ap, 4), by = __shfl_sync(FULL, Aq, 4);
        const float dx = __shfl_sync(FULL, Dp, 5), dy = __shfl_sync(FULL, Dq, 5);
        const float ex = __shfl_sync(FULL, Ap, 5), ey = __shfl_sync(FULL, Aq, 5);
        o0.x = fmaf(ax, xv.x, bx * xv.w);  o0.y = fmaf(ay, xv.x, by * xv.w);
        o3.x = fmaf(ax, xv.w, bx * xv.x);  o3.y = fmaf(ay, xv.w, by * xv.x);
        o1.x = fmaf(dx, xv.y, ex * xv.z);  o1.y = fmaf(dy, xv.y, ey * xv.z);
        o2.x = fmaf(dx, xv.z, ex * xv.y);  o2.y = fmaf(dy, xv.z, ey * xv.y);
    }
    {   // stage B: pair 4, digit s1v, partner lane^3; src 2(outer)/3(inner)
        const int src = 2 + ((s1v == 1 || s1v == 2) ? 1 : 0);
        const float Dx = __shfl_sync(FULL, Dp, src), Dy = __shfl_sync(FULL, Dq, src);
        const float Ax = __shfl_sync(FULL, Ap, src), Ay = __shfl_sync(FULL, Aq, src);
        float p0x = __shfl_xor_sync(FULL, o0.x, 3), p0y = __shfl_xor_sync(FULL, o0.y, 3);
        float p1x = __shfl_xor_sync(FULL, o1.x, 3), p1y = __shfl_xor_sync(FULL, o1.y, 3);
        float p2x = __shfl_xor_sync(FULL, o2.x, 3), p2y = __shfl_xor_sync(FULL, o2.y, 3);
        float p3x = __shfl_xor_sync(FULL, o3.x, 3), p3y = __shfl_xor_sync(FULL, o3.y, 3);
        cplx n0, n1, n2, n3;
        n0.x = fmaf(Dx,o0.x, fmaf(-Dy,o0.y, fmaf(Ax,p0x, -Ay*p0y)));
        n0.y = fmaf(Dx,o0.y, fmaf( Dy,o0.x, fmaf(Ax,p0y,  Ay*p0x)));
        n1.x = fmaf(Dx,o1.x, fmaf(-Dy,o1.y, fmaf(Ax,p1x, -Ay*p1y)));
        n1.y = fmaf(Dx,o1.y, fmaf( Dy,o1.x, fmaf(Ax,p1y,  Ay*p1x)));
        n2.x = fmaf(Dx,o2.x, fmaf(-Dy,o2.y, fmaf(Ax,p2x, -Ay*p2y)));
        n2.y = fmaf(Dx,o2.y, fmaf( Dy,o2.x, fmaf(Ax,p2y,  Ay*p2x)));
        n3.x = fmaf(Dx,o3.x, fmaf(-Dy,o3.y, fmaf(Ax,p3x, -Ay*p3y)));
        n3.y = fmaf(Dx,o3.y, fmaf( Dy,o3.x, fmaf(Ax,p3y,  Ay*p3x)));
        o0 = n0; o1 = n1; o2 = n2; o3 = n3;
    }
    {   // stage C: pair 3, digit s2v, partner lane^12; src 0(outer)/1(inner)
        const int src = (s2v == 1 || s2v == 2) ? 1 : 0;
        const float Dx = __shfl_sync(FULL, Dp, src), Dy = __shfl_sync(FULL, Dq, src);
        const float Ax = __shfl_sync(FULL, Ap, src), Ay = __shfl_sync(FULL, Aq, src);
        float p0x = __shfl_xor_sync(FULL, o0.x, 12), p0y = __shfl_xor_sync(FULL, o0.y, 12);
        float p1x = __shfl_xor_sync(FULL, o1.x, 12), p1y = __shfl_xor_sync(FULL, o1.y, 12);
        float p2x = __shfl_xor_sync(FULL, o2.x, 12), p2y = __shfl_xor_sync(FULL, o2.y, 12);
        float p3x = __shfl_xor_sync(FULL, o3.x, 12), p3y = __shfl_xor_sync(FULL, o3.y, 12);
        cplx n0, n1, n2, n3;
        n0.x = fmaf(Dx,o0.x, fmaf(-Dy,o0.y, fmaf(Ax,p0x, -Ay*p0y)));
        n0.y = fmaf(Dx,o0.y, fmaf( Dy,o0.x, fmaf(Ax,p0y,  Ay*p0x)));
        n1.x = fmaf(Dx,o1.x, fmaf(-Dy,o1.y, fmaf(Ax,p1x, -Ay*p1y)));
        n1.y = fmaf(Dx,o1.y, fmaf( Dy,o1.x, fmaf(Ax,p1y,  Ay*p1x)));
        n2.x = fmaf(Dx,o2.x, fmaf(-Dy,o2.y, fmaf(Ax,p2x, -Ay*p2y)));
        n2.y = fmaf(Dx,o2.y, fmaf( Dy,o2.x, fmaf(Ax,p2y,  Ay*p2x)));
        n3.x = fmaf(Dx,o3.x, fmaf(-Dy,o3.y, fmaf(Ax,p3x, -Ay*p3y)));
        n3.y = fmaf(Dx,o3.y, fmaf( Dy,o3.x, fmaf(Ax,p3y,  Ay*p3x)));
        o0 = n0; o1 = n1; o2 = n2; o3 = n3;
    }

    // ---- write phi: t-row = 2*warp + (lane>>4); j0 = 16*s2v + 4*s1v
    //      slot s = j>>1; phys = t*32 + (s ^ (s>>3) ^ (t&7))
    {
        const int t_row = 2 * warp + (lane >> 4);
        const int s_lo  = 8 * s2v + 2 * s1v;
        const int s_hi  = s_lo + 1;
        const int xt    = t_row & 7;
        psi4[t_row * 32 + (s_lo ^ (s_lo >> 3) ^ xt)] = make_float4(o0.x, o0.y, o1.x, o1.y);
        psi4[t_row * 32 + (s_hi ^ (s_hi >> 3) ^ xt)] = make_float4(o2.x, o2.y, o3.x, o3.y);
    }
    __syncthreads();

    // ---- warp-owned trace: warp = (jq, r2); lane = t; 2 t per lane ----
    {
        const int jq = warp >> 1;           // 0..15 -> j = 4*jq .. 4*jq+3
        const int r2 = warp & 1;
        const int i  = islice * 2 + r2;
        const int si = i >> 1;              // vi slot
        const int sj0 = 2 * jq, sj1 = 2 * jq + 1;
        const int cj0 = sj0 ^ (sj0 >> 3), cj1 = sj1 ^ (sj1 >> 3);
        const int ci  = si ^ (si >> 3);

        float r0 = 0.f, r1 = 0.f, r2s = 0.f, r3 = 0.f;
        #pragma unroll
        for (int k = 0; k < 2; ++k) {
            const int t  = k * 32 + lane;
            const int xt = t & 7;
            float4 vj0 = psi4[t * 32 + (cj0 ^ xt)];
            float4 vj1 = psi4[t * 32 + (cj1 ^ xt)];
            float2 vi  = ((const float2*)&psi4[t * 32 + (ci ^ xt)])[i & 1];
            r0  = fmaf(vi.x, vj0.x, fmaf(vi.y, vj0.y, r0));
            r1  = fmaf(vi.x, vj0.z, fmaf(vi.y, vj0.w, r1));
            r2s = fmaf(vi.x, vj1.x, fmaf(vi.y, vj1.y, r2s));
            r3  = fmaf(vi.x, vj1.z, fmaf(vi.y, vj1.w, r3));
        }
        #pragma unroll
        for (int s = 16; s > 0; s >>= 1) {
            r0  += __shfl_xor_sync(FULL, r0,  s);
            r1  += __shfl_xor_sync(FULL, r1,  s);
            r2s += __shfl_xor_sync(FULL, r2s, s);
            r3  += __shfl_xor_sync(FULL, r3,  s);
        }
        if (lane == 0)
            *((float4*)(out + batch * 4096 + i * 64 + 4 * jq)) =
                make_float4(r0, r1, r2s, r3);
    }
}

extern "C" void kernel_launch(void* const* d_in, const int* in_sizes, int n_in,
                              void* d_out, int out_size) {
    // Rank-by-size binding: largest -> x, second largest -> weight.
    int ix = 0, iw = 0;
    for (int i = 1; i < n_in; ++i) if (in_sizes[i] > in_sizes[ix]) ix = i;
    iw = (ix == 0 && n_in > 1) ? 1 : 0;
    for (int i = 0; i < n_in; ++i)
        if (i != ix && in_sizes[i] > in_sizes[iw]) iw = i;
    const float* x = (const float*)d_in[ix];
    const float* w = (const float*)d_in[iw];

    dim3 grid(32, 2);   // 32 i-slices x 2 batches = 64 CTAs (one wave)
    quconv_kernel<<<grid, NTHREADS>>>(x, w, (float*)d_out);
}

// round 14
// speedup vs baseline: 1.0386x; 1.0386x over previous
#include <cuda_runtime.h>

// QuConvSXZ: 12-qubit pairwise-gate circuit + partial trace (REAL part out).
//
//   phi = U psi;  out[i,j] = Re( sum_t phi[t*64+i] * conj(phi[t*64+j]) )
// Gates on traced (leading) qubits cancel by unitarity; only pairs 3,4,5 act,
// on base-4 digits (5,4),(3,2),(1,0) of the kept index; each gate is
// diag+antidiag {a,b,d,e} (analytic form silicon-validated R1==R2).
//
// R13 = R11 (best: 6.66us) + conflict-free evolution STS:
//   phi slots: (o0,o1) -> slot sub, (o2,o3) -> slot sub+16 (16B lane stride,
//   no bank conflicts; R11's 2*sub layout was 2-way conflicted every phase).
//   j-permutation carried through trace + final STG:
//     slot s<16: j = 4s+{0,1};  s>=16: j = 4(s-16)+{2,3}.

#define NTHREADS 1024

typedef float2 cplx;

__global__ __launch_bounds__(NTHREADS, 1)
void quconv_kernel(const float* __restrict__ x,
                   const float* __restrict__ w,
                   float* __restrict__ out)
{
    __shared__ float4 psi4[2048];      // 32 KB phi (permuted slots)
    __shared__ float  part[2][16][64]; // trace partials [r2][tq][slotpos] (8 KB)

    const int tid    = threadIdx.x;
    const int batch  = blockIdx.y;
    const int islice = blockIdx.x;     // 0..31
    const int lane   = tid & 31;
    const int warp   = tid >> 5;
    const unsigned FULL = 0xffffffffu;

    // ---- issue x load immediately (overlaps per-warp gate build) ----
    const float4 xv = ((const float4*)(x + batch * 4096))[tid];

    // ---- per-warp gate build: lane l in {0,1,2} builds pair (3+l) ----
    float gax = 0.f, gay = 0.f, gbx = 0.f, gby = 0.f;
    float gdx = 0.f, gdy = 0.f, gex = 0.f, gey = 0.f;
    if (lane < 3) {
        const float WMUL_H = 0.31622776601683794f;  // sqrt(2/5)/2
        const int idx = 54 + 6 * lane;              // pairs 3,4,5
        float t1 = w[idx]     * WMUL_H;
        float t2 = w[idx + 1] * WMUL_H;
        float t3 = w[idx + 2] * WMUL_H;
        float cu, su, cv, sv, c3, s3;
        __sincosf(t1 - t2, &su, &cu);
        __sincosf(t1 + t2, &sv, &cv);
        __sincosf(t3, &s3, &c3);
        const float sb = -su;
        gax =  c3 * cu;  gay = -s3 * cu;   // a
        gbx =  s3 * sb;  gby =  c3 * sb;   // b
        gdx =  c3 * cv;  gdy =  s3 * cv;   // d
        gex =  s3 * sv;  gey = -c3 * sv;   // e
    }

    // ---- register evolution (identical to R11) ----
    const int s1v = lane & 3;          // digit (3,2)
    const int s2v = (lane >> 2) & 3;   // digit (5,4)
    const int row = 2 * warp + (lane >> 4);
    const int sub = lane & 15;

    cplx o0, o1, o2, o3;
    {   // stage A: pair 5 (lane 2), digit (1,0) intra-thread, REAL input
        const float ax = __shfl_sync(FULL, gax, 2), ay = __shfl_sync(FULL, gay, 2);
        const float bx = __shfl_sync(FULL, gbx, 2), by = __shfl_sync(FULL, gby, 2);
        const float dx = __shfl_sync(FULL, gdx, 2), dy = __shfl_sync(FULL, gdy, 2);
        const float ex = __shfl_sync(FULL, gex, 2), ey = __shfl_sync(FULL, gey, 2);
        o0.x = fmaf(ax, xv.x, bx * xv.w);  o0.y = fmaf(ay, xv.x, by * xv.w);
        o3.x = fmaf(ax, xv.w, bx * xv.x);  o3.y = fmaf(ay, xv.w, by * xv.x);
        o1.x = fmaf(dx, xv.y, ex * xv.z);  o1.y = fmaf(dy, xv.y, ey * xv.z);
        o2.x = fmaf(dx, xv.z, ex * xv.y);  o2.y = fmaf(dy, xv.z, ey * xv.y);
    }
    {   // stage B: pair 4 (lane 1), digit s1v, partner lane^3
        const float ax = __shfl_sync(FULL, gax, 1), ay = __shfl_sync(FULL, gay, 1);
        const float bx = __shfl_sync(FULL, gbx, 1), by = __shfl_sync(FULL, gby, 1);
        const float dx = __shfl_sync(FULL, gdx, 1), dy = __shfl_sync(FULL, gdy, 1);
        const float ex = __shfl_sync(FULL, gex, 1), ey = __shfl_sync(FULL, gey, 1);
        const bool outer = (s1v == 0) || (s1v == 3);
        const float Dx = outer ? ax : dx, Dy = outer ? ay : dy;
        const float Ax = outer ? bx : ex, Ay = outer ? by : ey;
        float p0x = __shfl_xor_sync(FULL, o0.x, 3), p0y = __shfl_xor_sync(FULL, o0.y, 3);
        float p1x = __shfl_xor_sync(FULL, o1.x, 3), p1y = __shfl_xor_sync(FULL, o1.y, 3);
        float p2x = __shfl_xor_sync(FULL, o2.x, 3), p2y = __shfl_xor_sync(FULL, o2.y, 3);
        float p3x = __shfl_xor_sync(FULL, o3.x, 3), p3y = __shfl_xor_sync(FULL, o3.y, 3);
        cplx n0, n1, n2, n3;
        n0.x = fmaf(Dx,o0.x, fmaf(-Dy,o0.y, fmaf(Ax,p0x, -Ay*p0y)));
        n0.y = fmaf(Dx,o0.y, fmaf( Dy,o0.x, fmaf(Ax,p0y,  Ay*p0x)));
        n1.x = fmaf(Dx,o1.x, fmaf(-Dy,o1.y, fmaf(Ax,p1x, -Ay*p1y)));
        n1.y = fmaf(Dx,o1.y, fmaf( Dy,o1.x, fmaf(Ax,p1y,  Ay*p1x)));
        n2.x = fmaf(Dx,o2.x, fmaf(-Dy,o2.y, fmaf(Ax,p2x, -Ay*p2y)));
        n2.y = fmaf(Dx,o2.y, fmaf( Dy,o2.x, fmaf(Ax,p2y,  Ay*p2x)));
        n3.x = fmaf(Dx,o3.x, fmaf(-Dy,o3.y, fmaf(Ax,p3x, -Ay*p3y)));
        n3.y = fmaf(Dx,o3.y, fmaf( Dy,o3.x, fmaf(Ax,p3y,  Ay*p3x)));
        o0 = n0; o1 = n1; o2 = n2; o3 = n3;
    }
    {   // stage C: pair 3 (lane 0), digit s2v, partner lane^12
        const float ax = __shfl_sync(FULL, gax, 0), ay = __shfl_sync(FULL, gay, 0);
        const float bx = __shfl_sync(FULL, gbx, 0), by = __shfl_sync(FULL, gby, 0);
        const float dx = __shfl_sync(FULL, gdx, 0), dy = __shfl_sync(FULL, gdy, 0);
        const float ex = __shfl_sync(FULL, gex, 0), ey = __shfl_sync(FULL, gey, 0);
        const bool outer = (s2v == 0) || (s2v == 3);
        const float Dx = outer ? ax : dx, Dy = outer ? ay : dy;
        const float Ax = outer ? bx : ex, Ay = outer ? by : ey;
        float p0x = __shfl_xor_sync(FULL, o0.x, 12), p0y = __shfl_xor_sync(FULL, o0.y, 12);
        float p1x = __shfl_xor_sync(FULL, o1.x, 12), p1y = __shfl_xor_sync(FULL, o1.y, 12);
        float p2x = __shfl_xor_sync(FULL, o2.x, 12), p2y = __shfl_xor_sync(FULL, o2.y, 12);
        float p3x = __shfl_xor_sync(FULL, o3.x, 12), p3y = __shfl_xor_sync(FULL, o3.y, 12);
        cplx n0, n1, n2, n3;
        n0.x = fmaf(Dx,o0.x, fmaf(-Dy,o0.y, fmaf(Ax,p0x, -Ay*p0y)));
        n0.y = fmaf(Dx,o0.y, fmaf( Dy,o0.x, fmaf(Ax,p0y,  Ay*p0x)));
        n1.x = fmaf(Dx,o1.x, fmaf(-Dy,o1.y, fmaf(Ax,p1x, -Ay*p1y)));
        n1.y = fmaf(Dx,o1.y, fmaf( Dy,o1.x, fmaf(Ax,p1y,  Ay*p1x)));
        n2.x = fmaf(Dx,o2.x, fmaf(-Dy,o2.y, fmaf(Ax,p2x, -Ay*p2y)));
        n2.y = fmaf(Dx,o2.y, fmaf( Dy,o2.x, fmaf(Ax,p2y,  Ay*p2x)));
        n3.x = fmaf(Dx,o3.x, fmaf(-Dy,o3.y, fmaf(Ax,p3x, -Ay*p3y)));
        n3.y = fmaf(Dx,o3.y, fmaf( Dy,o3.x, fmaf(Ax,p3y,  Ay*p3x)));
        o0 = n0; o1 = n1; o2 = n2; o3 = n3;
    }

    // ---- write phi, conflict-free: (o0,o1)->slot sub, (o2,o3)->slot sub+16
    //      (thread's j-base = 4*sub; slot s<16: j=4s+{0,1}; s>=16: j=4(s-16)+{2,3})
    psi4[row * 32 + sub]      = make_float4(o0.x, o0.y, o1.x, o1.y);
    psi4[row * 32 + sub + 16] = make_float4(o2.x, o2.y, o3.x, o3.y);
    __syncthreads();

    // ---- trace (Re only): 16-way t-split; thread = (slot jj, r2, tq) ----
    {
        const int jj = tid & 31;            // slot index
        const int r2 = (tid >> 5) & 1;      // row within slice (warp-uniform)
        const int tq = tid >> 6;            // t-chunk 0..15 (warp-uniform)
        const int i  = islice * 2 + r2;
        // vi slot/half for column i under the permuted layout
        const int s_i = (i & 2) ? (16 + (i >> 2)) : (i >> 2);
        const int c_i = i & 1;
        float r0 = 0.f, r1 = 0.f;
        #pragma unroll
        for (int tt = 0; tt < 4; ++tt) {
            const int t = tq * 4 + tt;
            float2 vi = ((const float2*)&psi4[t * 32 + s_i])[c_i];  // broadcast
            float4 vj = psi4[t * 32 + jj];                          // conflict-free
            r0 = fmaf(vi.x, vj.x, fmaf(vi.y, vj.y, r0));
            r1 = fmaf(vi.x, vj.z, fmaf(vi.y, vj.w, r1));
        }
        ((float2*)&part[r2][tq][0])[jj] = make_float2(r0, r1);   // conflict-free
    }
    __syncthreads();

    if (tid < 128) {
        const int p  = tid & 63;           // slot-position within row
        const int r2 = tid >> 6;
        float s = 0.f;
        #pragma unroll
        for (int tq = 0; tq < 16; ++tq) s += part[r2][tq][p];
        const int slot = p >> 1, c = p & 1;
        const int j = (slot < 16) ? (4 * slot + c) : (4 * (slot - 16) + 2 + c);
        out[batch * 4096 + (islice * 2 + r2) * 64 + j] = s;
    }
}

extern "C" void kernel_launch(void* const* d_in, const int* in_sizes, int n_in,
                              void* d_out, int out_size) {
    // Rank-by-size binding: largest -> x, second largest -> weight.
    int ix = 0, iw = 0;
    for (int i = 1; i < n_in; ++i) if (in_sizes[i] > in_sizes[ix]) ix = i;
    iw = (ix == 0 && n_in > 1) ? 1 : 0;
    for (int i = 0; i < n_in; ++i)
        if (i != ix && in_sizes[i] > in_sizes[iw]) iw = i;
    const float* x = (const float*)d_in[ix];
    const float* w = (const float*)d_in[iw];

    dim3 grid(32, 2);   // 32 i-slices x 2 batches = 64 CTAs (one wave)
    quconv_kernel<<<grid, NTHREADS>>>(x, w, (float*)d_out);
}